// round 11
// baseline (speedup 1.0000x reference)
#include <cuda_runtime.h>
#include <cuda_bf16.h>
#include <math.h>

// Problem constants: x [16, 256, 128, 128] fp32, w [1, 2, 7, 7] fp32
// out [16, 1, 128, 128] fp32
#define B_  16
#define C_  256
#define H_  128
#define W_  128
#define HW_ (H_ * W_)          // 16384
#define HW4_ (HW_ / 4)         // 4096 float4 groups per plane
#define NCHUNK 4
#define CPC (C_ / NCHUNK)      // 64 channels per chunk-lane

// Conv tiling: 16 rows x 32 cols per block -> 512 blocks.
#define HT  16                 // output rows per tile
#define TRR (HT + 6)           // input rows incl. vertical halo = 22
#define GT  10                 // float4 groups incl. horizontal halo (8 + 2)
#define NIT (2 * TRR * GT)     // 440 items per block

// Final mean/max planes [B][2][HW] = 2 MB (no chunk partials anymore)
__device__ float g_s[B_ * 2 * HW_];

// ---------------------------------------------------------------------------
// Kernel 1: FULL channel mean+max in one pass. 1024 blocks x 256 threads.
// Block = 64 spatial float4 groups of one batch; threads = 4 chunk-lanes x 64
// groups. Each thread reduces 64 channels to registers; cross-chunk combine
// via 8 KB smem; final planes written straight to g_s (2 MB).
// ---------------------------------------------------------------------------
__global__ __launch_bounds__(256) void reduce_full_kernel(const float* __restrict__ x) {
    __shared__ float4 s_sum[NCHUNK][64];   // 4 KB
    __shared__ float4 s_max[NCHUNK][64];   // 4 KB

    int b       = blockIdx.x >> 6;                 // 64 blocks per batch
    int sp4base = (blockIdx.x & 63) * 64;          // first float4 group
    int chunk   = threadIdx.x >> 6;                // 0..3
    int g       = threadIdx.x & 63;                // group lane

    const float4* base = reinterpret_cast<const float4*>(x)
                       + (size_t)b * C_ * HW4_ + (size_t)chunk * CPC * HW4_
                       + sp4base + g;

    float4 sum = make_float4(0.f, 0.f, 0.f, 0.f);
    float4 mx  = make_float4(-INFINITY, -INFINITY, -INFINITY, -INFINITY);

    #pragma unroll 8
    for (int c = 0; c < CPC; ++c) {
        float4 v = __ldcs(base + c * HW4_);        // streaming, evict-first
        sum.x += v.x; sum.y += v.y; sum.z += v.z; sum.w += v.w;
        mx.x = fmaxf(mx.x, v.x); mx.y = fmaxf(mx.y, v.y);
        mx.z = fmaxf(mx.z, v.z); mx.w = fmaxf(mx.w, v.w);
    }

    s_sum[chunk][g] = sum;
    s_max[chunk][g] = mx;
    __syncthreads();

    if (threadIdx.x < 64) {                        // mean combine
        int gg = threadIdx.x;
        float4 a = s_sum[0][gg], b2 = s_sum[1][gg], c2 = s_sum[2][gg], d = s_sum[3][gg];
        const float inv = 1.0f / (float)C_;
        float4 v;
        v.x = (a.x + b2.x + c2.x + d.x) * inv;
        v.y = (a.y + b2.y + c2.y + d.y) * inv;
        v.z = (a.z + b2.z + c2.z + d.z) * inv;
        v.w = (a.w + b2.w + c2.w + d.w) * inv;
        reinterpret_cast<float4*>(g_s)[(size_t)b * 2 * HW4_ + sp4base + gg] = v;
    } else if (threadIdx.x < 128) {                // max combine
        int gg = threadIdx.x - 64;
        float4 a = s_max[0][gg], b2 = s_max[1][gg], c2 = s_max[2][gg], d = s_max[3][gg];
        float4 v;
        v.x = fmaxf(fmaxf(a.x, b2.x), fmaxf(c2.x, d.x));
        v.y = fmaxf(fmaxf(a.y, b2.y), fmaxf(c2.y, d.y));
        v.z = fmaxf(fmaxf(a.z, b2.z), fmaxf(c2.z, d.z));
        v.w = fmaxf(fmaxf(a.w, b2.w), fmaxf(c2.w, d.w));
        reinterpret_cast<float4*>(g_s)[(size_t)b * 2 * HW4_ + HW4_ + sp4base + gg] = v;
    }
}

// ---------------------------------------------------------------------------
// Kernel 2: stage mean/max tile (vert+horiz halo, zero-padded) into smem
// (1 LDG.128 per item now), then 7x7 2-ch conv + sigmoid, 4-wide blocked.
// 512 blocks x 256 threads; block = 16 rows x 32 cols of one batch.
// ---------------------------------------------------------------------------
__global__ __launch_bounds__(256) void conv_sigmoid_kernel(const float* __restrict__ wgt,
                                                           float* __restrict__ out) {
    __shared__ float4 sm[2][TRR][GT];  // 7 KB
    __shared__ float  ws[98];

    if (threadIdx.x < 98) ws[threadIdx.x] = __ldg(wgt + threadIdx.x);

    int bid = blockIdx.x;
    int b   = bid >> 5;                // batch
    int rem = bid & 31;
    int ht  = rem >> 2;                // 0..7  (h tile)
    int wt  = rem & 3;                 // 0..3  (w tile)
    int h0  = ht * HT;                 // first output row
    int w0g = wt * 8;                  // first output float4 group
    int gb  = w0g - 1;                 // first halo group (may be -1)

    const float4* pb = reinterpret_cast<const float4*>(g_s) + (size_t)b * 2 * HW4_;

    // ---- Stage phase: 440 items, <=2 per thread, loads batched ----
    {
        float4 val[2];
        int    pl[2], rr[2], jj[2];
        bool   own[2];

        #pragma unroll
        for (int k = 0; k < 2; ++k) {
            int i = threadIdx.x + k * 256;
            own[k] = (i < NIT);
            if (own[k]) {
                int plane = i / (TRR * GT);            // boundary at 220
                int r2    = i - plane * (TRR * GT);
                int r     = r2 / GT;
                int j     = r2 - r * GT;
                int hh    = h0 - 3 + r;
                int gg    = gb + j;
                pl[k] = plane; rr[k] = r; jj[k] = j;
                bool valid = ((unsigned)hh < (unsigned)H_) && ((unsigned)gg < 32u);
                float4 v = make_float4(0.f, 0.f, 0.f, 0.f);
                if (valid)
                    v = __ldg(pb + (size_t)plane * HW4_ + hh * 32 + gg);
                val[k] = v;
            }
        }
        #pragma unroll
        for (int k = 0; k < 2; ++k)
            if (own[k]) sm[pl[k]][rr[k]][jj[k]] = val[k];
    }
    __syncthreads();

    // ---- Conv phase: threads 0..127 -> (row r, output group j), 4 px each ----
    if (threadIdx.x < 128) {
        int r = threadIdx.x >> 3;          // 0..15
        int j = threadIdx.x & 7;           // 0..7

        float acc0 = 0.f, acc1 = 0.f, acc2 = 0.f, acc3 = 0.f;

        #pragma unroll
        for (int ch = 0; ch < 2; ++ch) {
            const float* wp = ws + ch * 49;
            #pragma unroll
            for (int kh = 0; kh < 7; ++kh) {
                float4 lo  = sm[ch][r + kh][j];        // halo (zero-padded)
                float4 mid = sm[ch][r + kh][j + 1];
                float4 hi  = sm[ch][r + kh][j + 2];
                float v[12] = { lo.x, lo.y, lo.z, lo.w,
                                mid.x, mid.y, mid.z, mid.w,
                                hi.x, hi.y, hi.z, hi.w };
                #pragma unroll
                for (int kw = 0; kw < 7; ++kw) {
                    float wv = wp[kh * 7 + kw];
                    acc0 = fmaf(v[kw + 1], wv, acc0);
                    acc1 = fmaf(v[kw + 2], wv, acc1);
                    acc2 = fmaf(v[kw + 3], wv, acc2);
                    acc3 = fmaf(v[kw + 4], wv, acc3);
                }
            }
        }

        float4 res;
        res.x = 1.0f / (1.0f + __expf(-acc0));
        res.y = 1.0f / (1.0f + __expf(-acc1));
        res.z = 1.0f / (1.0f + __expf(-acc2));
        res.w = 1.0f / (1.0f + __expf(-acc3));
        reinterpret_cast<float4*>(out)[(size_t)b * HW4_ + (h0 + r) * 32 + w0g + j] = res;
    }
}

extern "C" void kernel_launch(void* const* d_in, const int* in_sizes, int n_in,
                              void* d_out, int out_size) {
    const float* x = (const float*)d_in[0];
    const float* w = (const float*)d_in[1];
    float* out = (float*)d_out;

    reduce_full_kernel<<<1024, 256>>>(x);         // one-pass mean+max
    conv_sigmoid_kernel<<<512, 256>>>(w, out);    // conv + sigmoid
}